// round 1
// baseline (speedup 1.0000x reference)
#include <cuda_runtime.h>
#include <cuda_bf16.h>
#include <cstdint>

// out[b, 0:64] = full_input[b, idx[b]*64 : (idx[b]+1)*64]
// B = 262144, OUTPUT_DIM = 64, NB_CTRL_SIG = 16, fp32.
// Pure gather: one float4 per thread, 16 float4 per row.

static constexpr int BATCH = 262144;
static constexpr int OUT_DIM = 64;            // floats per output row
static constexpr int IN_ROW = 64 * 16;        // 1024 floats per input row
static constexpr int VEC_PER_ROW = OUT_DIM / 4;  // 16 float4 per row

__global__ void __launch_bounds__(256) multiplexer_gather_kernel(
    const float4* __restrict__ in,      // [BATCH, IN_ROW/4] as float4
    const int*    __restrict__ indices, // [BATCH]
    float4*       __restrict__ out)     // [BATCH, VEC_PER_ROW]
{
    const uint32_t gid = blockIdx.x * blockDim.x + threadIdx.x;
    const uint32_t row  = gid >> 4;        // which batch row
    const uint32_t lane = gid & 15u;       // which float4 within the 64-float block

    // indices[row]: 16 consecutive threads share the same row -> L1 broadcast
    const int idx = __ldg(&indices[row]);

    // input row = IN_ROW floats = 256 float4; selected block starts at idx*16 float4
    const uint32_t src = row * (IN_ROW / 4) + (uint32_t)idx * VEC_PER_ROW + lane;
    out[gid] = in[src];
}

extern "C" void kernel_launch(void* const* d_in, const int* in_sizes, int n_in,
                              void* d_out, int out_size) {
    const float4* in      = (const float4*)d_in[0];
    const int*    indices = (const int*)d_in[1];
    float4*       out     = (float4*)d_out;

    const int total_vec = BATCH * VEC_PER_ROW;   // 4,194,304 threads
    const int threads = 256;
    const int blocks = total_vec / threads;      // 16384 blocks

    multiplexer_gather_kernel<<<blocks, threads>>>(in, indices, out);
}

// round 2
// speedup vs baseline: 1.2212x; 1.2212x over previous
#include <cuda_runtime.h>
#include <cuda_bf16.h>
#include <cstdint>

// out[b, 0:64] = full_input[b, idx[b]*64 : (idx[b]+1)*64]
// B = 262144, OUTPUT_DIM = 64, NB_CTRL_SIG = 16, fp32.
// v2: 4 independent row-gathers per thread to raise MLP (latency hiding),
// chunks strided across the grid so each chunk remains fully coalesced.

static constexpr int BATCH = 262144;
static constexpr int OUT_DIM = 64;               // floats per output row
static constexpr int IN_ROW_VEC = (64 * 16) / 4; // 256 float4 per input row
static constexpr int VEC_PER_ROW = OUT_DIM / 4;  // 16 float4 per output row
static constexpr int TOTAL_VEC = BATCH * VEC_PER_ROW; // 4,194,304
static constexpr int UNROLL = 4;
static constexpr int STRIDE = TOTAL_VEC / UNROLL;     // 1,048,576

__global__ void __launch_bounds__(256) multiplexer_gather_v2(
    const float4* __restrict__ in,      // [BATCH, 256] float4
    const int*    __restrict__ indices, // [BATCH]
    float4*       __restrict__ out)     // [TOTAL_VEC] float4
{
    const uint32_t base = blockIdx.x * blockDim.x + threadIdx.x;

    uint32_t vid[UNROLL];
    int      idx[UNROLL];

    // Phase 1: 4 independent index loads (front-batched by ptxas)
    #pragma unroll
    for (int u = 0; u < UNROLL; u++) {
        vid[u] = base + u * (uint32_t)STRIDE;
        idx[u] = __ldg(&indices[vid[u] >> 4]);
    }

    // Phase 2: 4 independent data loads -> MLP = 4
    float4 v[UNROLL];
    #pragma unroll
    for (int u = 0; u < UNROLL; u++) {
        const uint32_t row  = vid[u] >> 4;
        const uint32_t lane = vid[u] & 15u;
        v[u] = in[row * IN_ROW_VEC + (uint32_t)idx[u] * VEC_PER_ROW + lane];
    }

    // Phase 3: 4 coalesced stores
    #pragma unroll
    for (int u = 0; u < UNROLL; u++) {
        out[vid[u]] = v[u];
    }
}

extern "C" void kernel_launch(void* const* d_in, const int* in_sizes, int n_in,
                              void* d_out, int out_size) {
    const float4* in      = (const float4*)d_in[0];
    const int*    indices = (const int*)d_in[1];
    float4*       out     = (float4*)d_out;

    const int threads = 256;
    const int blocks  = STRIDE / threads;   // 4096 blocks
    multiplexer_gather_v2<<<blocks, threads>>>(in, indices, out);
}

// round 3
// speedup vs baseline: 1.3417x; 1.0986x over previous
#include <cuda_runtime.h>
#include <cuda_bf16.h>
#include <cstdint>

// out[b, 0:64] = full_input[b, idx[b]*64 : (idx[b]+1)*64]
// B = 262144, OUTPUT_DIM = 64, NB_CTRL_SIG = 16, fp32.
// v3: 8 rows per thread (consecutive), indices loaded as 2x int4 (LDG.128),
// 8 independent data LDG.128 in flight per thread.

static constexpr int BATCH = 262144;
static constexpr int IN_ROW_VEC = 256;   // float4 per input row (1024 floats)
static constexpr int VEC_PER_ROW = 16;   // float4 per output row (64 floats)
static constexpr int UNROLL = 8;         // rows per thread

__global__ void __launch_bounds__(256) multiplexer_gather_v3(
    const float4* __restrict__ in,       // [BATCH, 256] float4
    const int4*   __restrict__ idx4,     // [BATCH/4] int4 view of indices
    float4*       __restrict__ out)      // [BATCH*16] float4
{
    const uint32_t t    = blockIdx.x * blockDim.x + threadIdx.x;
    const uint32_t g    = t >> 4;        // group of 8 consecutive rows
    const uint32_t lane = t & 15u;       // float4 slot within the 64-float block
    const uint32_t row0 = g * UNROLL;

    // Phase 1: two vector index loads (16-way broadcast within lane group)
    const int4 ia = __ldg(&idx4[2 * g + 0]);   // indices for rows row0..row0+3
    const int4 ib = __ldg(&idx4[2 * g + 1]);   // indices for rows row0+4..row0+7

    int idx[UNROLL] = { ia.x, ia.y, ia.z, ia.w, ib.x, ib.y, ib.z, ib.w };

    // Phase 2: 8 independent data loads -> high MLP
    float4 v[UNROLL];
    #pragma unroll
    for (int u = 0; u < UNROLL; u++) {
        const uint32_t row = row0 + u;
        v[u] = __ldg(&in[row * IN_ROW_VEC + (uint32_t)idx[u] * VEC_PER_ROW + lane]);
    }

    // Phase 3: 8 coalesced stores (256B contiguous per lane group)
    #pragma unroll
    for (int u = 0; u < UNROLL; u++) {
        out[(row0 + u) * VEC_PER_ROW + lane] = v[u];
    }
}

extern "C" void kernel_launch(void* const* d_in, const int* in_sizes, int n_in,
                              void* d_out, int out_size) {
    const float4* in   = (const float4*)d_in[0];
    const int4*   idx4 = (const int4*)d_in[1];
    float4*       out  = (float4*)d_out;

    const int total_threads = BATCH * VEC_PER_ROW / UNROLL;  // 524288
    const int threads = 256;
    const int blocks  = total_threads / threads;             // 2048
    multiplexer_gather_v3<<<blocks, threads>>>(in, idx4, out);
}